// round 3
// baseline (speedup 1.0000x reference)
#include <cuda_runtime.h>
#include <cstdint>

// Problem constants
#define B       256
#define NH      12
#define S       197
#define SS      (S * S)          // 38809
#define NP      196              // patches
#define CUTOFF  98               // top half
#define IMG     224
#define CH      3
#define PER_IMG (CH * IMG * IMG)        // 150528
#define PER_IMG4 (PER_IMG / 4)          // 37632
#define TOTAL4  (B * PER_IMG4)          // 9,633,792

// Scratch: per-(batch,patch) float mask. 256*196*4 = ~200 KB, L2-resident.
__device__ float g_mask[B * NP];

// Kernel 1: CLS-attention head-sum + top-98 selection per batch.
// One block per batch. Thread p handles patch p.
__global__ void __launch_bounds__(256, 4)
attn_mask_kernel(const float* __restrict__ x)
{
    __shared__ float attn[NP];
    const int b = blockIdx.x;
    const int p = threadIdx.x;

    if (p < NP) {
        // x[b, h, 0, 1+p] = x + b*NH*SS + h*SS + (1+p)
        const float* base = x + (size_t)b * (NH * SS) + 1 + p;
        float s = 0.f;
        #pragma unroll
        for (int h = 0; h < NH; ++h)
            s += __ldg(base + h * SS);
        attn[p] = s;
    }
    __syncthreads();

    if (p < NP) {
        const float v = attn[p];
        int cnt = 0;
        // rank = #values strictly greater, ties broken toward lower index
        // (matches top_k preferring lower indices on ties)
        #pragma unroll 7
        for (int q = 0; q < NP; ++q) {
            const float u = attn[q];
            cnt += (u > v) || (u == v && q < p);
        }
        g_mask[b * NP + p] = (cnt < CUTOFF) ? 1.0f : 0.0f;
    }
}

// Kernel 2: elementwise masked copy, float4 per thread.
// Pixel layout [B, C, H=224, W=224]; a float4 (4 consecutive W-pixels at
// 4-aligned offset) always falls inside a single 16-wide patch column.
__global__ void __launch_bounds__(256)
apply_mask_kernel(const float4* __restrict__ img, float4* __restrict__ out)
{
    const int idx = blockIdx.x * blockDim.x + threadIdx.x;
    if (idx >= TOTAL4) return;

    const int b  = idx / PER_IMG4;
    int r        = idx - b * PER_IMG4;      // float4 index within image
    const int rc = r % (IMG * IMG / 4);     // within channel (12544)
    const int y  = rc / (IMG / 4);          // row (0..223)
    const int x4 = rc - y * (IMG / 4);      // float4 col (0..55)

    // patch row = y>>4, patch col = (x4*4)>>4 = x4>>2
    const int patch = ((y >> 4) * 14) + (x4 >> 2);
    const float m = g_mask[b * NP + patch];

    float4 v = __ldg(img + idx);
    v.x *= m; v.y *= m; v.z *= m; v.w *= m;
    out[idx] = v;
}

extern "C" void kernel_launch(void* const* d_in, const int* in_sizes, int n_in,
                              void* d_out, int out_size)
{
    const float* x   = (const float*)d_in[0];   // [256,12,197,197]
    const float* img = (const float*)d_in[1];   // [256,3,224,224]
    float* out       = (float*)d_out;           // [256, 150528]

    attn_mask_kernel<<<B, 256>>>(x);

    const int blocks = (TOTAL4 + 255) / 256;    // 37632 exactly
    apply_mask_kernel<<<blocks, 256>>>((const float4*)img, (float4*)out);
}